// round 7
// baseline (speedup 1.0000x reference)
#include <cuda_runtime.h>
#include <math.h>

#define BATCH 4
#define NPTS  8192
#define KNB   16
#define NPOS  (BATCH*NPTS*KNB)   // 524288
#define NQ    (BATCH*NPTS)       // 32768
#define CAP   48
#define NPART 4

__device__ int g_idx[NQ*KNB];
__device__ unsigned long long g_sbuf[(long long)NQ*NPART*CAP];
__device__ int g_scnt[NQ*NPART];

typedef unsigned long long u64;

__device__ __forceinline__ u64 pk2(float x, float y) {
    u64 r; asm("mov.b64 %0,{%1,%2};" : "=l"(r) : "f"(x), "f"(y)); return r;
}
__device__ __forceinline__ float2 up2(u64 v) {
    float2 r; asm("mov.b64 {%0,%1},%2;" : "=f"(r.x), "=f"(r.y) : "l"(v)); return r;
}
__device__ __forceinline__ void fma2(u64& d, u64 a, u64 b) {
    asm("fma.rn.f32x2 %0,%1,%2,%0;" : "+l"(d) : "l"(a), "l"(b));
}
__device__ __forceinline__ float leaky(float v) { return v >= 0.f ? v : 0.2f*v; }

// =====================================================================
// KNN part 1 (unchanged from R6): branchless 2-pass top-16 per quarter
// =====================================================================
__global__ __launch_bounds__(128) void knn_part(const float* __restrict__ xyz)
{
    extern __shared__ float4 tile[];
    const int tid = threadIdx.x;
    const int quarter = blockIdx.x & 3;
    const int qb = (blockIdx.x >> 2) & 63;
    const int b  = blockIdx.x >> 8;
    const int i  = qb*128 + tid;
    const float* xb = xyz + b*3*NPTS;
    const int c0 = quarter*2048;

    for (int l = tid; l < 512; l += 128) {
        float4 vx = ((const float4*)(xb + c0))[l];
        float4 vy = ((const float4*)(xb + NPTS + c0))[l];
        float4 vz = ((const float4*)(xb + 2*NPTS + c0))[l];
        tile[4*l+0] = make_float4(vx.x, vy.x, vz.x, fmaf(vx.x,vx.x, fmaf(vy.x,vy.x, vz.x*vz.x)));
        tile[4*l+1] = make_float4(vx.y, vy.y, vz.y, fmaf(vx.y,vx.y, fmaf(vy.y,vy.y, vz.y*vz.y)));
        tile[4*l+2] = make_float4(vx.z, vy.z, vz.z, fmaf(vx.z,vx.z, fmaf(vy.z,vy.z, vz.z*vz.z)));
        tile[4*l+3] = make_float4(vx.w, vy.w, vz.w, fmaf(vx.w,vx.w, fmaf(vy.w,vy.w, vz.w*vz.w)));
    }
    __syncthreads();

    const float x2 = -2.0f*xb[i], y2 = -2.0f*xb[NPTS+i], z2 = -2.0f*xb[2*NPTS+i];

    float s[32];
#pragma unroll
    for (int t = 0; t < 32; t++) s[t] = 3.4e38f;
    for (int j0 = 0; j0 < 2048; j0 += 32) {
#pragma unroll
        for (int u = 0; u < 32; u++) {
            float4 p = tile[j0+u];
            float d = fmaf(x2, p.x, fmaf(y2, p.y, fmaf(z2, p.z, p.w)));
            s[u] = fminf(s[u], d);
        }
    }

#pragma unroll
    for (int k = 2; k <= 32; k <<= 1) {
#pragma unroll
        for (int j = k >> 1; j > 0; j >>= 1) {
#pragma unroll
            for (int ii = 0; ii < 32; ii++) {
                int l = ii ^ j;
                if (l > ii) {
                    float lo = fminf(s[ii], s[l]);
                    float hi = fmaxf(s[ii], s[l]);
                    bool up = ((ii & k) == 0);
                    s[ii] = up ? lo : hi;
                    s[l]  = up ? hi : lo;
                }
            }
        }
    }
    const float T = s[15];

    u64 buf[CAP];
    int cnt = 0, ovf = 0;
    for (int j = 0; j < 2048; j++) {
        float4 p = tile[j];
        float d = fmaf(x2, p.x, fmaf(y2, p.y, fmaf(z2, p.z, p.w)));
        if (d <= T) {
            if (cnt < CAP) { buf[cnt] = pk2(d, __int_as_float(c0+j)); cnt++; }
            else ovf = 1;
        }
    }

    if (ovf) {
        float bd[16]; int bj[16];
#pragma unroll
        for (int t = 0; t < 16; t++) { bd[t] = 3.4e38f; bj[t] = 0; }
        float cm = 3.4e38f;
        for (int j = 0; j < 2048; j++) {
            float4 p = tile[j];
            float d = fmaf(x2, p.x, fmaf(y2, p.y, fmaf(z2, p.z, p.w)));
            if (d < cm) {
                int am = 0; float mv = bd[0];
#pragma unroll
                for (int u = 1; u < 16; u++) if (bd[u] > mv) { mv = bd[u]; am = u; }
#pragma unroll
                for (int u = 0; u < 16; u++) if (u == am) { bd[u] = d; bj[u] = c0 + j; }
                cm = bd[0];
#pragma unroll
                for (int u = 1; u < 16; u++) cm = fmaxf(cm, bd[u]);
            }
        }
        cnt = 16;
#pragma unroll
        for (int t = 0; t < 16; t++) buf[t] = pk2(bd[t], __int_as_float(bj[t]));
    }

    const int qg = b*NPTS + i;
    g_scnt[qg*NPART + quarter] = cnt;
    u64* dst = g_sbuf + (long long)(qg*NPART + quarter)*CAP;
    for (int t = 0; t < cnt; t++) dst[t] = buf[t];
}

// =====================================================================
// KNN part 2 (unchanged)
// =====================================================================
__global__ __launch_bounds__(256) void knn_merge()
{
    const int q = blockIdx.x*256 + threadIdx.x;
    float bd[16]; int bj[16];
#pragma unroll
    for (int t = 0; t < 16; t++) { bd[t] = 3.4e38f; bj[t] = 0; }
    float cm = 3.4e38f;
#pragma unroll
    for (int h = 0; h < NPART; h++) {
        const int c = g_scnt[q*NPART + h];
        const u64* src = g_sbuf + (long long)(q*NPART + h)*CAP;
        for (int e = 0; e < c; e++) {
            float2 v = up2(src[e]);
            float d = v.x;
            if (d < cm) {
                int am = 0; float mv = bd[0];
#pragma unroll
                for (int u = 1; u < 16; u++) if (bd[u] > mv) { mv = bd[u]; am = u; }
#pragma unroll
                for (int u = 0; u < 16; u++) if (u == am) { bd[u] = d; bj[u] = __float_as_int(v.y); }
                cm = bd[0];
#pragma unroll
                for (int u = 1; u < 16; u++) cm = fmaxf(cm, bd[u]);
            }
        }
    }
#pragma unroll
    for (int t = 0; t < 16; t++) g_idx[q*16 + t] = bj[t];
}

// =====================================================================
// smem layout (floats) — fused kernel, 256 threads, 2 CTAs/SM
// =====================================================================
#define SA    0        // 4352
#define SB    4352     // 4352
#define SC    8704     // 4352
#define SW0   13056    // 4352 ping
#define SW1   17408    // 4352 pong
#define SX1   21760    // 256
#define SBIAS 22016    // 256
#define SMEM_FLOATS 22272   // 89088 B -> 2 CTAs/SM

// ---- weight loaders: LDG->regs (4 float4/thread), STS k-major ----
// A-type: 64 outs x 64 k (stride 68)
template<int KFULL>
__device__ __forceinline__ void ldgA(float4 r[4], const float* __restrict__ src,
                                     int koff, int tid)
{
#pragma unroll
    for (int it = 0; it < 4; it++) {
        int l = it*256 + tid;
        int o = l & 63, k4 = l >> 6;
        r[it] = *(const float4*)(src + o*KFULL + koff + 4*k4);
    }
}
__device__ __forceinline__ void stsA(float* __restrict__ dst, const float4 r[4], int tid)
{
#pragma unroll
    for (int it = 0; it < 4; it++) {
        int l = it*256 + tid;
        int o = l & 63, k = (l >> 6)*4;
        dst[(k  )*68+o] = r[it].x; dst[(k+1)*68+o] = r[it].y;
        dst[(k+2)*68+o] = r[it].z; dst[(k+3)*68+o] = r[it].w;
    }
}
// B-type: 128 outs x 32 k (stride 132)
template<int KFULL>
__device__ __forceinline__ void ldgB(float4 r[4], const float* __restrict__ src,
                                     int koff, int tid)
{
#pragma unroll
    for (int it = 0; it < 4; it++) {
        int l = it*256 + tid;
        int o = l & 127, k4 = l >> 7;
        r[it] = *(const float4*)(src + o*KFULL + koff + 4*k4);
    }
}
__device__ __forceinline__ void stsB(float* __restrict__ dst, const float4 r[4], int tid)
{
#pragma unroll
    for (int it = 0; it < 4; it++) {
        int l = it*256 + tid;
        int o = l & 127, k = (l >> 7)*4;
        dst[(k  )*132+o] = r[it].x; dst[(k+1)*132+o] = r[it].y;
        dst[(k+2)*132+o] = r[it].z; dst[(k+3)*132+o] = r[it].w;
    }
}

// 8 outs (4 pairs) x 4 pos, K=32. w: [k][o] stride 132.
__device__ __forceinline__ void gemmB32(const float* __restrict__ w,
                                        const float* __restrict__ a,
                                        int og, int pg, u64 acc[4][4])
{
#pragma unroll 4
    for (int k = 0; k < 32; k++) {
        const float* wr = w + k*132 + og*8;
        ulonglong2 w01 = *(const ulonglong2*)wr;
        ulonglong2 w23 = *(const ulonglong2*)(wr+4);
        u64 wp[4] = {w01.x,w01.y,w23.x,w23.y};
        float4 av = *(const float4*)(a + k*68 + pg*4);
        u64 as[4] = {pk2(av.x,av.x), pk2(av.y,av.y), pk2(av.z,av.z), pk2(av.w,av.w)};
#pragma unroll
        for (int op = 0; op < 4; op++)
#pragma unroll
            for (int p = 0; p < 4; p++) fma2(acc[op][p], wp[op], as[p]);
    }
}

// 4 outs (2 pairs) x 4 pos, K=64. w: [k][o] stride 68.
__device__ __forceinline__ void gemmA64(const float* __restrict__ w,
                                        const float* __restrict__ a,
                                        int og, int pg, u64 acc[2][4])
{
#pragma unroll 4
    for (int k = 0; k < 64; k++) {
        ulonglong2 w01 = *(const ulonglong2*)(w + k*68 + og*4);
        u64 wp[2] = {w01.x, w01.y};
        float4 av = *(const float4*)(a + k*68 + pg*4);
        u64 as[4] = {pk2(av.x,av.x), pk2(av.y,av.y), pk2(av.z,av.z), pk2(av.w,av.w)};
#pragma unroll
        for (int op = 0; op < 2; op++)
#pragma unroll
            for (int p = 0; p < 4; p++) fma2(acc[op][p], wp[op], as[p]);
    }
}

// =====================================================================
// Fused kernel: 64-pos tile, 256 threads (8 warps), 2 CTAs/SM
// =====================================================================
__global__ void __launch_bounds__(256,2) fused_kernel(
    const float* __restrict__ xyz,
    const float* __restrict__ w1sc, const float* __restrict__ b1sc,
    const float* __restrict__ w1a,  const float* __restrict__ b1a,
    const float* __restrict__ w1b,  const float* __restrict__ b1b,
    const float* __restrict__ w1c,  const float* __restrict__ b1c,
    const float* __restrict__ w2sc, const float* __restrict__ b2sc,
    const float* __restrict__ w2a,  const float* __restrict__ b2a,
    const float* __restrict__ w2b,  const float* __restrict__ b2b,
    const float* __restrict__ w2c,  const float* __restrict__ b2c,
    float* __restrict__ outp)
{
    extern __shared__ float sm[];
    const int tid = threadIdx.x;
    const int pg = tid & 15, og = tid >> 4;   // og 0..15, pg 0..15
    const int base = blockIdx.x << 6;
    const int b  = base >> 17;
    const int n0 = (base & (NPTS*KNB - 1)) >> 4;
    const int nl = pg >> 2;                   // thread's 4 pos share n = n0+nl

    float4 R[4];

    // ---- Pro: LDG w1b ; feats + small weights + biases -> SC ----
    ldgA<64>(R, w1b, 0, tid);
    for (int l = tid; l < 640; l += 256) {
        int o = l/10, k = l - o*10;
        sm[SC + 680  + k*68 + o] = w1sc[l];
        sm[SC + 1360 + k*68 + o] = w1a[l];
    }
    if (tid < 64) {
        sm[SBIAS+tid] = b1sc[tid]; sm[SBIAS+64+tid] = b1a[tid];
        sm[SBIAS+128+tid] = b1b[tid]; sm[SBIAS+192+tid] = b1c[tid];
    }
    if (tid < 64) {
        int nn = n0 + (tid >> 4);
        const float* xb = xyz + b*3*NPTS;
        int j = g_idx[(b*NPTS + nn)*KNB + (tid & 15)];
        float cx = xb[nn], cy = xb[NPTS+nn], cz = xb[2*NPTS+nn];
        float nx = xb[j],  ny = xb[NPTS+j],  nz = xb[2*NPTS+j];
        float rx = nx-cx, ry = ny-cy, rz = nz-cz;
        float dd = sqrtf(fmaf(rx,rx, fmaf(ry,ry, rz*rz)) + 1e-12f);
        sm[SC+0*68+tid]=cx; sm[SC+1*68+tid]=cy; sm[SC+2*68+tid]=cz;
        sm[SC+3*68+tid]=nx; sm[SC+4*68+tid]=ny; sm[SC+5*68+tid]=nz;
        sm[SC+6*68+tid]=rx; sm[SC+7*68+tid]=ry; sm[SC+8*68+tid]=rz;
        sm[SC+9*68+tid]=dd;
    }
    __syncthreads();

    // ---- PK10: STS w1b->SW0 ; LDG w1c ; stage1 sc+a (K=10) ; h->SA sc->SB ----
    stsA(sm + SW0, R, tid);
    ldgA<64>(R, w1c, 0, tid);
    {
        u64 accS[2][4], accA[2][4];
#pragma unroll
        for (int op=0;op<2;op++)
#pragma unroll
            for (int p=0;p<4;p++) { accS[op][p]=0ull; accA[op][p]=0ull; }
#pragma unroll
        for (int k = 0; k < 10; k++) {
            ulonglong2 ws = *(const ulonglong2*)(sm + SC + 680  + k*68 + og*4);
            ulonglong2 wa = *(const ulonglong2*)(sm + SC + 1360 + k*68 + og*4);
            float4 av = *(const float4*)(sm + SC + k*68 + pg*4);
            u64 as[4] = {pk2(av.x,av.x), pk2(av.y,av.y), pk2(av.z,av.z), pk2(av.w,av.w)};
            u64 wsp[2] = {ws.x, ws.y}, wap[2] = {wa.x, wa.y};
#pragma unroll
            for (int op=0;op<2;op++)
#pragma unroll
                for (int p=0;p<4;p++) { fma2(accS[op][p], wsp[op], as[p]); fma2(accA[op][p], wap[op], as[p]); }
        }
#pragma unroll
        for (int op=0;op<2;op++) {
            int o0 = og*4 + 2*op;
            float ba0 = sm[SBIAS+64+o0], ba1 = sm[SBIAS+64+o0+1];
#pragma unroll
            for (int p=0;p<4;p++) {
                float2 va = up2(accA[op][p]);
                sm[SA + (o0  )*68 + pg*4 + p] = leaky(va.x + ba0);
                sm[SA + (o0+1)*68 + pg*4 + p] = leaky(va.y + ba1);
                float2 vs = up2(accS[op][p]);
                sm[SB + (o0  )*68 + pg*4 + p] = vs.x;
                sm[SB + (o0+1)*68 + pg*4 + p] = vs.y;
            }
        }
    }
    __syncthreads();

    u64 acc2[2][4];
#define ZERO2 {_Pragma("unroll") for (int op=0;op<2;op++) _Pragma("unroll") for (int p=0;p<4;p++) acc2[op][p]=0ull;}

    // ---- G1 [SW0=w1b]: stage1-b on SA(h) ; h2->SC ----
    stsA(sm + SW1, R, tid);          // w1c
    ldgA<128>(R, w2a, 0, tid);       // w2a main
    ZERO2
    gemmA64(sm + SW0, sm + SA, og, pg, acc2);
#pragma unroll
    for (int op=0;op<2;op++) {
        int o0 = og*4 + 2*op;
        float b0 = sm[SBIAS+128+o0], b1 = sm[SBIAS+128+o0+1];
#pragma unroll
        for (int p=0;p<4;p++) {
            float2 v = up2(acc2[op][p]);
            sm[SC + (o0  )*68 + pg*4 + p] = leaky(v.x + b0);
            sm[SC + (o0+1)*68 + pg*4 + p] = leaky(v.y + b1);
        }
    }
    __syncthreads();

    // ---- G2 [SW1=w1c]: stage1-c on SC(h2) ; out1->SB (+sc) ; x1 ----
    stsA(sm + SW0, R, tid);          // w2a main
    ldgA<128>(R, w2a, 64, tid);      // w2a corr cols
    ZERO2
    gemmA64(sm + SW1, sm + SC, og, pg, acc2);
#pragma unroll
    for (int op=0;op<2;op++) {
        int o0 = og*4 + 2*op;
        float bt0 = sm[SBIAS+192+o0] + sm[SBIAS+o0];
        float bt1 = sm[SBIAS+192+o0+1] + sm[SBIAS+o0+1];
        float v0m = -3.4e38f, v1m = -3.4e38f;
#pragma unroll
        for (int p=0;p<4;p++) {
            float2 v = up2(acc2[op][p]);
            float o0v = v.x + sm[SB + (o0  )*68 + pg*4 + p] + bt0;
            float o1v = v.y + sm[SB + (o0+1)*68 + pg*4 + p] + bt1;
            sm[SB + (o0  )*68 + pg*4 + p] = o0v;
            sm[SB + (o0+1)*68 + pg*4 + p] = o1v;
            v0m = fmaxf(v0m, o0v); v1m = fmaxf(v1m, o1v);
        }
        v0m = fmaxf(v0m, __shfl_xor_sync(0xffffffffu, v0m, 1));
        v0m = fmaxf(v0m, __shfl_xor_sync(0xffffffffu, v0m, 2));
        v1m = fmaxf(v1m, __shfl_xor_sync(0xffffffffu, v1m, 1));
        v1m = fmaxf(v1m, __shfl_xor_sync(0xffffffffu, v1m, 2));
        if ((pg & 3) == 0) {
            sm[SX1 + (o0  )*4 + nl] = v0m;
            sm[SX1 + (o0+1)*4 + nl] = v1m;
        }
    }
    __syncthreads();

    // ---- G3 [SW0=w2a main]: stage2-a main on SB(out1) ----
    stsA(sm + SW1, R, tid);          // w2a corr
    ldgB<64>(R, w2b, 0, tid);        // w2b chunk0
    u64 accA2[2][4];
#pragma unroll
    for (int op=0;op<2;op++)
#pragma unroll
        for (int p=0;p<4;p++) accA2[op][p]=0ull;
    gemmA64(sm + SW0, sm + SB, og, pg, accA2);
    __syncthreads();

    // ---- G4 [SW1=w2a corr]: x1-corr ; h -> SA ----
    stsB(sm + SW0, R, tid);          // w2b chunk0
    ldgB<64>(R, w2b, 32, tid);       // w2b chunk1
    {
        u64 crA[2] = {0,0};
#pragma unroll 4
        for (int c = 0; c < 64; c++) {
            ulonglong2 w01 = *(const ulonglong2*)(sm + SW1 + c*68 + og*4);
            float xv = sm[SX1 + c*4 + nl];
            u64 xs = pk2(xv, xv);
            fma2(crA[0], w01.x, xs); fma2(crA[1], w01.y, xs);
        }
#pragma unroll
        for (int op=0;op<2;op++) {
            int o0 = og*4 + 2*op;
            float2 c2 = up2(crA[op]);
            float b0 = __ldg(b2a + o0) + c2.x;
            float b1 = __ldg(b2a + o0 + 1) + c2.y;
#pragma unroll
            for (int p=0;p<4;p++) {
                float2 v = up2(accA2[op][p]);
                sm[SA + (o0  )*68 + pg*4 + p] = leaky(v.x + b0);
                sm[SA + (o0+1)*68 + pg*4 + p] = leaky(v.y + b1);
            }
        }
    }
    __syncthreads();

    // ---- G5/G6: stage2-b (two 32-k chunks) on SA(h) ----
    u64 accb[4][4];
#pragma unroll
    for (int op=0;op<4;op++)
#pragma unroll
        for (int p=0;p<4;p++) accb[op][p]=0ull;

    stsB(sm + SW1, R, tid);          // w2b chunk1
    ldgB<128>(R, w2c, 0, tid);       // w2c chunk0
    gemmB32(sm + SW0, sm + SA, og, pg, accb);
    __syncthreads();

    stsB(sm + SW0, R, tid);          // w2c chunk0
    ldgB<128>(R, w2c, 32, tid);      // w2c chunk1 (held across E1)
    gemmB32(sm + SW1, sm + SA + 32*68, og, pg, accb);
    __syncthreads();

    // ---- E1: h2 epilogue -> SA (ch<64) / SC (ch>=64) ----
    {
        float* dst = sm + ((og < 8) ? (SA + og*8*68) : (SC + (og-8)*8*68));
#pragma unroll
        for (int op=0;op<4;op++) {
            int o0 = og*8 + 2*op;
            float b0 = __ldg(b2b + o0), b1 = __ldg(b2b + o0+1);
#pragma unroll
            for (int p=0;p<4;p++) {
                float2 v = up2(accb[op][p]);
                dst[(2*op  )*68 + pg*4 + p] = leaky(v.x + b0);
                dst[(2*op+1)*68 + pg*4 + p] = leaky(v.y + b1);
            }
        }
    }
    __syncthreads();

    // ---- G7..G12: stage2 c (4 chunks) + sc main (2 chunks), one acc ----
    u64 acc[4][4];
#pragma unroll
    for (int op=0;op<4;op++)
#pragma unroll
        for (int p=0;p<4;p++) acc[op][p]=0ull;

    stsB(sm + SW1, R, tid);          // w2c chunk1
    ldgB<128>(R, w2c, 64, tid);
    gemmB32(sm + SW0, sm + SA, og, pg, acc);            // c k0-31 (h2 lo)
    __syncthreads();

    stsB(sm + SW0, R, tid);          // w2c chunk2
    ldgB<128>(R, w2c, 96, tid);
    gemmB32(sm + SW1, sm + SA + 32*68, og, pg, acc);    // c k32-63
    __syncthreads();

    stsB(sm + SW1, R, tid);          // w2c chunk3
    ldgB<128>(R, w2sc, 0, tid);
    gemmB32(sm + SW0, sm + SC, og, pg, acc);            // c k64-95 (h2 hi)
    __syncthreads();

    stsB(sm + SW0, R, tid);          // w2sc chunk0
    ldgB<128>(R, w2sc, 32, tid);
    gemmB32(sm + SW1, sm + SC + 32*68, og, pg, acc);    // c k96-127
    __syncthreads();

    stsB(sm + SW1, R, tid);          // w2sc chunk1
    ldgB<128>(R, w2sc, 64, tid);
    gemmB32(sm + SW0, sm + SB, og, pg, acc);            // sc k0-31 (out1)
    __syncthreads();

    stsB(sm + SW0, R, tid);          // w2sc corr chunk0 (cols 64-95)
    ldgB<128>(R, w2sc, 96, tid);
    gemmB32(sm + SW1, sm + SB + 32*68, og, pg, acc);    // sc k32-63
    __syncthreads();

    // ---- G13/G14: sc x1-corr (2 x 32 cols) ----
    u64 cr2[4] = {0,0,0,0};
    stsB(sm + SW1, R, tid);          // w2sc corr chunk1 (cols 96-127)
#pragma unroll 4
    for (int c = 0; c < 32; c++) {
        const float* wr = sm + SW0 + c*132 + og*8;
        ulonglong2 w01 = *(const ulonglong2*)wr;
        ulonglong2 w23 = *(const ulonglong2*)(wr+4);
        float xv = sm[SX1 + c*4 + nl];
        u64 xs = pk2(xv, xv);
        fma2(cr2[0], w01.x, xs); fma2(cr2[1], w01.y, xs);
        fma2(cr2[2], w23.x, xs); fma2(cr2[3], w23.y, xs);
    }
    __syncthreads();
#pragma unroll 4
    for (int c = 0; c < 32; c++) {
        const float* wr = sm + SW1 + c*132 + og*8;
        ulonglong2 w01 = *(const ulonglong2*)wr;
        ulonglong2 w23 = *(const ulonglong2*)(wr+4);
        float xv = sm[SX1 + (32+c)*4 + nl];
        u64 xs = pk2(xv, xv);
        fma2(cr2[0], w01.x, xs); fma2(cr2[1], w01.y, xs);
        fma2(cr2[2], w23.x, xs); fma2(cr2[3], w23.y, xs);
    }

    // ---- final epilogue: +biases +corr, max over 16 k, write ----
#pragma unroll
    for (int op=0;op<4;op++) {
        int o0 = og*8 + 2*op;
        float2 c2 = up2(cr2[op]);
        float bt0 = __ldg(b2sc + o0)     + __ldg(b2c + o0)     + c2.x;
        float bt1 = __ldg(b2sc + o0 + 1) + __ldg(b2c + o0 + 1) + c2.y;
        float m0 = -3.4e38f, m1 = -3.4e38f;
#pragma unroll
        for (int p=0;p<4;p++) {
            float2 v = up2(acc[op][p]);
            m0 = fmaxf(m0, v.x); m1 = fmaxf(m1, v.y);
        }
        m0 += bt0; m1 += bt1;
        m0 = fmaxf(m0, __shfl_xor_sync(0xffffffffu, m0, 1));
        m0 = fmaxf(m0, __shfl_xor_sync(0xffffffffu, m0, 2));
        m1 = fmaxf(m1, __shfl_xor_sync(0xffffffffu, m1, 1));
        m1 = fmaxf(m1, __shfl_xor_sync(0xffffffffu, m1, 2));
        if ((pg & 3) == 0) {
            outp[((long long)b*128 + o0    )*NPTS + n0 + nl] = m0;
            outp[((long long)b*128 + o0 + 1)*NPTS + n0 + nl] = m1;
        }
    }
}

// =====================================================================
extern "C" void kernel_launch(void* const* d_in, const int* in_sizes, int n_in,
                              void* d_out, int out_size)
{
    const float* xyz     = (const float*)d_in[0];
    const float* p1_sc_w = (const float*)d_in[1];
    const float* p1_sc_b = (const float*)d_in[2];
    const float* p1_a_w  = (const float*)d_in[3];
    const float* p1_a_b  = (const float*)d_in[4];
    const float* p1_b_w  = (const float*)d_in[5];
    const float* p1_b_b  = (const float*)d_in[6];
    const float* p1_c_w  = (const float*)d_in[7];
    const float* p1_c_b  = (const float*)d_in[8];
    const float* p2_sc_w = (const float*)d_in[9];
    const float* p2_sc_b = (const float*)d_in[10];
    const float* p2_a_w  = (const float*)d_in[11];
    const float* p2_a_b  = (const float*)d_in[12];
    const float* p2_b_w  = (const float*)d_in[13];
    const float* p2_b_b  = (const float*)d_in[14];
    const float* p2_c_w  = (const float*)d_in[15];
    const float* p2_c_b  = (const float*)d_in[16];
    float* outp = (float*)d_out;

    cudaFuncSetAttribute(fused_kernel, cudaFuncAttributeMaxDynamicSharedMemorySize,
                         SMEM_FLOATS*4);

    knn_part<<<BATCH*64*NPART, 128, 32768>>>(xyz);
    knn_merge<<<NQ/256, 256>>>();
    fused_kernel<<<NPOS/64, 256, SMEM_FLOATS*4>>>(
        xyz,
        p1_sc_w, p1_sc_b, p1_a_w, p1_a_b, p1_b_w, p1_b_b, p1_c_w, p1_c_b,
        p2_sc_w, p2_sc_b, p2_a_w, p2_a_b, p2_b_w, p2_b_b, p2_c_w, p2_c_b,
        outp);
}